// round 7
// baseline (speedup 1.0000x reference)
#include <cuda_runtime.h>
#include <cuda_fp16.h>
#include <cstdint>

// ============================================================================
// Problem constants
// ============================================================================
#define KDIM 4096
#define NDIM 4096
#define MDIM 4096        // B*S
#define NB   128         // N / 32
#define KB   128         // K / 32
#define NG   32          // N / 128 (4 nb rows per group)

#define STAGES 4
#define A_BYTES (128 * 32 * 2)     // 8192  A tile [128m x 32k] fp16
#define W_BYTES (128 * 32 * 2)     // 8192  W tile [128n x 32k] fp16
#define STAGE_BYTES (A_BYTES + W_BYTES)            // 16384
#define SMEM_KLIST 0                               // 512B (128 packed entries)
#define SMEM_BIAS  512                             // 512B (128 floats)
#define SMEM_STAGE 1024
#define SMEM_TOTAL (SMEM_STAGE + STAGES * STAGE_BYTES)  // 66560 -> 2 CTAs/SM

// ============================================================================
// Device globals
// ============================================================================
__device__ int g_bm[NB * KB];                    // block-active bitmap
__device__ int g_ulist[NG * KB];                 // per-ng union list: kb | (mask4<<8)
__device__ int g_ucount[NG];                     // per-ng union count
__device__ __half g_dh[(size_t)MDIM * KDIM];     // data  fp16 (32MB)
__device__ __half g_wh[(size_t)NDIM * KDIM];     // weight fp16 (active blocks only)

// ============================================================================
// Helpers
// ============================================================================
__device__ __forceinline__ uint32_t smem_u32(const void* p) {
    uint32_t a;
    asm("{ .reg .u64 t; cvta.to.shared.u64 t, %1; cvt.u32.u64 %0, t; }"
        : "=r"(a) : "l"(p));
    return a;
}

#define SWZ(off) ((uint32_t)(off) ^ ((((uint32_t)(off)) >> 3) & 0x70))

__device__ __forceinline__ void cp_async16(uint32_t saddr, const void* gaddr) {
    asm volatile("cp.async.cg.shared.global [%0], [%1], 16;"
                 :: "r"(saddr), "l"(gaddr) : "memory");
}
#define CP_ASYNC_COMMIT() asm volatile("cp.async.commit_group;" ::: "memory")
#define CP_ASYNC_WAIT(n)  asm volatile("cp.async.wait_group %0;" :: "n"(n) : "memory")

__device__ __forceinline__ void ldsm_x4(uint32_t addr, uint32_t* r) {
    asm volatile("ldmatrix.sync.aligned.m8n8.x4.shared.b16 {%0,%1,%2,%3}, [%4];"
                 : "=r"(r[0]), "=r"(r[1]), "=r"(r[2]), "=r"(r[3]) : "r"(addr));
}

// m16n8k16 fp16 mma, fp32 accum: D += A * B^T (row.col)
__device__ __forceinline__ void mma_f16(float* c, const uint32_t* a, const uint32_t* b) {
    asm volatile(
        "mma.sync.aligned.m16n8k16.row.col.f32.f16.f16.f32 "
        "{%0,%1,%2,%3}, {%4,%5,%6,%7}, {%8,%9}, {%0,%1,%2,%3};"
        : "+f"(c[0]), "+f"(c[1]), "+f"(c[2]), "+f"(c[3])
        : "r"(a[0]), "r"(a[1]), "r"(a[2]), "r"(a[3]), "r"(b[0]), "r"(b[1]));
}

// ============================================================================
// Kernel 1 (fused): mask pool (coalesced) + active-weight fp32->fp16 convert.
// One CTA (512 threads) per nb row-block.
// ============================================================================
__global__ __launch_bounds__(512) void mask_w_kernel(
    const int* __restrict__ mask, const float* __restrict__ weight) {
    __shared__ int sm_bm[KB];
    __shared__ int sm_list[KB];
    __shared__ int sm_cnt;
    const int nb = blockIdx.x;
    const int tid = threadIdx.x;

    if (tid < KB) sm_bm[tid] = 0;
    __syncthreads();

    // --- phase 1: coalesced mask scan; per-thread OR over 32 rows ---
    int acc0 = 0, acc1 = 0;
    const int* mrow = mask + (size_t)(nb * 32) * KDIM;
#pragma unroll 4
    for (int r = 0; r < 32; r++) {
        const int4* p = (const int4*)(mrow + (size_t)r * KDIM);
        int4 v0 = p[tid];
        int4 v1 = p[tid + 512];
        acc0 |= v0.x | v0.y | v0.z | v0.w;
        acc1 |= v1.x | v1.y | v1.z | v1.w;
    }
    if (acc0) sm_bm[tid >> 3] = 1;          // idempotent stores, no atomics
    if (acc1) sm_bm[64 + (tid >> 3)] = 1;
    __syncthreads();

    // --- write bitmap + build local active list ---
    if (tid < KB) g_bm[nb * KB + tid] = sm_bm[tid];
    if (tid == 0) {
        int c = 0;
        for (int kb = 0; kb < KB; kb++)
            if (sm_bm[kb]) sm_list[c++] = kb;
        sm_cnt = c;
    }
    __syncthreads();

    // --- phase 2: convert active blocks (32x32) to fp16 ---
    const int cnt = sm_cnt;
    const int row = tid >> 4;          // 0..31
    const int pos = (tid & 15) * 2;    // 0..30
    for (int j = 0; j < cnt; j++) {
        int kb = sm_list[j];
        size_t off = (size_t)(nb * 32 + row) * KDIM + (size_t)kb * 32 + pos;
        float2 v = *(const float2*)(weight + off);
        *(__half2*)(g_wh + off) = __floats2half2_rn(v.x, v.y);
    }
}

// ============================================================================
// Kernel 2: per-ng (4 nb rows) union k-list with 4-bit quarter mask.
// ============================================================================
__global__ __launch_bounds__(1024) void compact_union_kernel() {
    int ng = threadIdx.x >> 5;
    int lane = threadIdx.x & 31;
    int count = 0;
#pragma unroll
    for (int r = 0; r < 4; r++) {
        int kb = r * 32 + lane;
        int m4 = 0;
#pragma unroll
        for (int i = 0; i < 4; i++)
            m4 |= g_bm[(ng * 4 + i) * KB + kb] << i;
        unsigned bal = __ballot_sync(0xffffffffu, m4 != 0);
        int pos = count + __popc(bal & ((1u << lane) - 1u));
        if (m4) g_ulist[ng * KB + pos] = kb | (m4 << 8);
        count += __popc(bal);
    }
    if (lane == 0) g_ucount[ng] = count;
}

// ============================================================================
// Kernel 3: convert data fp32 -> fp16 (fully coalesced)
// ============================================================================
__global__ __launch_bounds__(256) void cvt_data_kernel(const float* __restrict__ in) {
    size_t base = ((size_t)blockIdx.x * 256 + threadIdx.x) * 16;
    const float4* s = (const float4*)(in + base);
    __half2 h[8];
#pragma unroll
    for (int i = 0; i < 4; i++) {
        float4 v = s[i];
        h[2 * i]     = __floats2half2_rn(v.x, v.y);
        h[2 * i + 1] = __floats2half2_rn(v.z, v.w);
    }
    uint4* d = (uint4*)(g_dh + base);
    d[0] = reinterpret_cast<uint4*>(h)[0];
    d[1] = reinterpret_cast<uint4*>(h)[1];
}

// ============================================================================
// Kernel 4: block-sparse fp16 GEMM with quarter-mask skipping.
// CTA: 128m x 128n (4 nb rows), 8 warps; warp = (m-half, n-quarter) -> 64m x 32n.
// grid = (ng=32, mtile=32). Active HMMA only; A read once per union kb.
// ============================================================================
__global__ __launch_bounds__(256, 2) void gemm_sparse_kernel(
    const float* __restrict__ bias,   // [N]
    float* __restrict__ out) {        // [M, N]
    extern __shared__ char smem[];
    const uint32_t sb = smem_u32(smem);
    const int tid = threadIdx.x;
    const int wid = tid >> 5;
    const int lane = tid & 31;
    const int ng = blockIdx.x;
    const int mtile = blockIdx.y;

    const int cnt = g_ucount[ng];
    if (tid < KB) ((int*)smem)[tid] = g_ulist[ng * KB + tid];
    if (tid < 128) ((float*)(smem + SMEM_BIAS))[tid] = bias[ng * 128 + tid];
    __syncthreads();
    const int* sk = (const int*)smem;

    const __half* Abase = g_dh + (size_t)(mtile * 128) * KDIM;
    const __half* Wbase = g_wh + (size_t)(ng * 128) * KDIM;

    // ---- stage loader: A 512 + W 512 16B chunks over 256 threads ----
    auto load_stage = [&](int s, int e) {
        const int kb = e & 0xFF;
        const int qm = e >> 8;
        const uint32_t aT = sb + SMEM_STAGE + s * STAGE_BYTES;
        const uint32_t wT = aT + A_BYTES;
        const __half* ag = Abase + kb * 32;
        const __half* wg = Wbase + kb * 32;
#pragma unroll
        for (int p = 0; p < 2; p++) {
            int c = tid + p * 256;           // 0..511
            int row = c >> 2, cc = c & 3;
            cp_async16(aT + SWZ(row * 64 + cc * 16),
                       ag + (size_t)row * KDIM + cc * 8);
        }
#pragma unroll
        for (int p = 0; p < 2; p++) {
            int c = tid + p * 256;
            int row = c >> 2, cc = c & 3;
            if ((qm >> (row >> 5)) & 1)      // load only active quarters
                cp_async16(wT + SWZ(row * 64 + cc * 16),
                           wg + (size_t)row * KDIM + cc * 8);
        }
    };

    float c_[4][4][4] = {};   // [m16-tile][n8-tile][frag]

    // ---- prologue ----
#pragma unroll
    for (int s0 = 0; s0 < STAGES - 1; s0++) {
        if (s0 < cnt) load_stage(s0, sk[s0]);
        CP_ASYNC_COMMIT();
    }

    const int q     = wid & 3;        // n-quarter
    const int mhalf = wid >> 2;       // m-half
    const int a_r  = (lane & 7) + ((lane >> 3) & 1) * 8;
    const int a_ch = lane >> 4;
    const int b_r  = ((lane >> 4) & 1) * 8 + (lane & 7);
    const int b_ch = (lane >> 3) & 1;

    int s = 0;
    for (int i = 0; i < cnt; i++) {
        CP_ASYNC_WAIT(STAGES - 2);
        __syncthreads();

        int jn = i + STAGES - 1;
        if (jn < cnt) load_stage((s + STAGES - 1) & (STAGES - 1), sk[jn]);
        CP_ASYNC_COMMIT();

        if ((sk[i] >> (8 + q)) & 1) {        // quarter active for this kb?
            const uint32_t aT = sb + SMEM_STAGE + s * STAGE_BYTES;
            const uint32_t wT = aT + A_BYTES;
#pragma unroll
            for (int j = 0; j < 2; j++) {    // two k16 steps
                uint32_t bx[4], by[4];
                int ch = 2 * j + b_ch;
                ldsm_x4(wT + SWZ((q * 32 + b_r) * 64 + ch * 16), bx);
                ldsm_x4(wT + SWZ((q * 32 + b_r + 16) * 64 + ch * 16), by);
                uint32_t bf[4][2] = {
                    {bx[0], bx[1]}, {bx[2], bx[3]},
                    {by[0], by[1]}, {by[2], by[3]}
                };
#pragma unroll
                for (int mt = 0; mt < 4; mt++) {
                    uint32_t af[4];
                    int row = mhalf * 64 + mt * 16 + a_r;
                    ldsm_x4(aT + SWZ(row * 64 + (2 * j + a_ch) * 16), af);
#pragma unroll
                    for (int nt = 0; nt < 4; nt++)
                        mma_f16(c_[mt][nt], af, bf[nt]);
                }
            }
        }
        s = (s + 1) & (STAGES - 1);
    }

    // ---- epilogue: bias (always, even for fully-inactive quarters) + store ----
    const float* sbias = (const float*)(smem + SMEM_BIAS);
    const int g = lane >> 2;
    const int qq = lane & 3;
#pragma unroll
    for (int mt = 0; mt < 4; mt++) {
        int row0 = mtile * 128 + mhalf * 64 + mt * 16 + g;
#pragma unroll
        for (int nt = 0; nt < 4; nt++) {
            int coll = q * 32 + nt * 8 + 2 * qq;
            float b0 = sbias[coll];
            float b1 = sbias[coll + 1];
            float2 v0 = make_float2(c_[mt][nt][0] + b0, c_[mt][nt][1] + b1);
            float2 v1 = make_float2(c_[mt][nt][2] + b0, c_[mt][nt][3] + b1);
            size_t col = (size_t)ng * 128 + coll;
            *(float2*)(out + (size_t)row0 * NDIM + col) = v0;
            *(float2*)(out + (size_t)(row0 + 8) * NDIM + col) = v1;
        }
    }
}

// ============================================================================
// Launch
// ============================================================================
extern "C" void kernel_launch(void* const* d_in, const int* in_sizes, int n_in,
                              void* d_out, int out_size) {
    const float* data   = (const float*)d_in[0];   // [B,S,K] -> [M,K]
    const int*   mask   = (const int*)d_in[1];     // [N,K]
    const float* weight = (const float*)d_in[2];   // [N,K]
    const float* bias   = (const float*)d_in[3];   // [N]
    float* out = (float*)d_out;                    // [M,N]

    mask_w_kernel<<<NB, 512>>>(mask, weight);
    cvt_data_kernel<<<4096, 256>>>(data);
    compact_union_kernel<<<1, 1024>>>();

    cudaFuncSetAttribute(gemm_sparse_kernel,
                         cudaFuncAttributeMaxDynamicSharedMemorySize, SMEM_TOTAL);
    dim3 grid(NG, MDIM / 128);     // x = ng, y = mtile
    gemm_sparse_kernel<<<grid, 256, SMEM_TOTAL>>>(bias, out);
}

// round 9
// speedup vs baseline: 1.3596x; 1.3596x over previous
#include <cuda_runtime.h>
#include <cuda_fp16.h>
#include <cstdint>

// ============================================================================
// Problem constants
// ============================================================================
#define KDIM 4096
#define NDIM 4096
#define MDIM 4096        // B*S
#define NB   128         // N / 32
#define KB   128         // K / 32

#define STAGES 3
#define A_BYTES (512 * 32 * 2)     // 32768  A tile [512m x 32k] fp16
#define W_BYTES (32 * 32 * 2)      // 2048   W tile [32n x 32k] fp16
#define STAGE_BYTES (A_BYTES + W_BYTES)            // 34816
#define SMEM_BIAS  512                             // 128B (32 floats)
#define SMEM_STAGE 1024
#define SMEM_TOTAL (SMEM_STAGE + STAGES * STAGE_BYTES)  // 105472 -> 2 CTAs/SM

// ============================================================================
// Device globals
// ============================================================================
__device__ int g_bm[NB * KB];                    // block-active bitmap
__device__ int g_klist[NB * KB];                 // per-nb compacted kb list
__device__ int g_kcount[NB];                     // per-nb active count
__device__ __half g_dh[(size_t)MDIM * KDIM];     // data  fp16 (32MB)
__device__ __half g_wh[(size_t)NDIM * KDIM];     // weight fp16 (active blocks only)

// ============================================================================
// Helpers
// ============================================================================
__device__ __forceinline__ uint32_t smem_u32(const void* p) {
    uint32_t a;
    asm("{ .reg .u64 t; cvta.to.shared.u64 t, %1; cvt.u32.u64 %0, t; }"
        : "=r"(a) : "l"(p));
    return a;
}

#define SWZ(off) ((uint32_t)(off) ^ ((((uint32_t)(off)) >> 3) & 0x70))

__device__ __forceinline__ void cp_async16(uint32_t saddr, const void* gaddr) {
    asm volatile("cp.async.cg.shared.global [%0], [%1], 16;"
                 :: "r"(saddr), "l"(gaddr) : "memory");
}
#define CP_ASYNC_COMMIT() asm volatile("cp.async.commit_group;" ::: "memory")
#define CP_ASYNC_WAIT(n)  asm volatile("cp.async.wait_group %0;" :: "n"(n) : "memory")

__device__ __forceinline__ void ldsm_x4(uint32_t addr, uint32_t* r) {
    asm volatile("ldmatrix.sync.aligned.m8n8.x4.shared.b16 {%0,%1,%2,%3}, [%4];"
                 : "=r"(r[0]), "=r"(r[1]), "=r"(r[2]), "=r"(r[3]) : "r"(addr));
}

// m16n8k16 fp16 mma, fp32 accum: D += A * B^T (row.col)
__device__ __forceinline__ void mma_f16(float* c, const uint32_t* a, const uint32_t* b) {
    asm volatile(
        "mma.sync.aligned.m16n8k16.row.col.f32.f16.f16.f32 "
        "{%0,%1,%2,%3}, {%4,%5,%6,%7}, {%8,%9}, {%0,%1,%2,%3};"
        : "+f"(c[0]), "+f"(c[1]), "+f"(c[2]), "+f"(c[3])
        : "r"(a[0]), "r"(a[1]), "r"(a[2]), "r"(a[3]), "r"(b[0]), "r"(b[1]));
}

// ============================================================================
// Kernel 1 (fused): mask pool (coalesced) + active-weight fp32->fp16 convert.
// One CTA (512 threads) per nb row-block.
// ============================================================================
__global__ __launch_bounds__(512) void mask_w_kernel(
    const int* __restrict__ mask, const float* __restrict__ weight) {
    __shared__ int sm_bm[KB];
    __shared__ int sm_list[KB];
    __shared__ int sm_cnt;
    const int nb = blockIdx.x;
    const int tid = threadIdx.x;

    if (tid < KB) sm_bm[tid] = 0;
    __syncthreads();

    // --- phase 1: coalesced mask scan; per-thread OR over 32 rows ---
    int acc0 = 0, acc1 = 0;
    const int* mrow = mask + (size_t)(nb * 32) * KDIM;
#pragma unroll 4
    for (int r = 0; r < 32; r++) {
        const int4* p = (const int4*)(mrow + (size_t)r * KDIM);
        int4 v0 = p[tid];
        int4 v1 = p[tid + 512];
        acc0 |= v0.x | v0.y | v0.z | v0.w;
        acc1 |= v1.x | v1.y | v1.z | v1.w;
    }
    if (acc0) sm_bm[tid >> 3] = 1;          // idempotent stores, no atomics
    if (acc1) sm_bm[64 + (tid >> 3)] = 1;
    __syncthreads();

    // --- write bitmap + build local active list ---
    if (tid < KB) g_bm[nb * KB + tid] = sm_bm[tid];
    if (tid == 0) {
        int c = 0;
        for (int kb = 0; kb < KB; kb++)
            if (sm_bm[kb]) sm_list[c++] = kb;
        sm_cnt = c;
    }
    __syncthreads();

    // --- phase 2: convert active blocks (32x32) to fp16 ---
    const int cnt = sm_cnt;
    const int row = tid >> 4;          // 0..31
    const int pos = (tid & 15) * 2;    // 0..30
    for (int j = 0; j < cnt; j++) {
        int kb = sm_list[j];
        size_t off = (size_t)(nb * 32 + row) * KDIM + (size_t)kb * 32 + pos;
        float2 v = *(const float2*)(weight + off);
        *(__half2*)(g_wh + off) = __floats2half2_rn(v.x, v.y);
    }
}

// ============================================================================
// Kernel 2: compact per-nb active kb list (deterministic order).
// 4 CTAs x 32 warps; warp per nb row.
// ============================================================================
__global__ __launch_bounds__(1024) void compact_kernel() {
    int nb = blockIdx.x * 32 + (threadIdx.x >> 5);
    int lane = threadIdx.x & 31;
    int count = 0;
#pragma unroll
    for (int r = 0; r < 4; r++) {
        int kb = r * 32 + lane;
        int a = g_bm[nb * KB + kb];
        unsigned bal = __ballot_sync(0xffffffffu, a);
        int pos = count + __popc(bal & ((1u << lane) - 1u));
        if (a) g_klist[nb * KB + pos] = kb;
        count += __popc(bal);
    }
    if (lane == 0) g_kcount[nb] = count;
}

// ============================================================================
// Kernel 3: convert data fp32 -> fp16 (fully coalesced)
// ============================================================================
__global__ __launch_bounds__(256) void cvt_data_kernel(const float* __restrict__ in) {
    size_t base = ((size_t)blockIdx.x * 256 + threadIdx.x) * 16;
    const float4* s = (const float4*)(in + base);
    __half2 h[8];
#pragma unroll
    for (int i = 0; i < 4; i++) {
        float4 v = s[i];
        h[2 * i]     = __floats2half2_rn(v.x, v.y);
        h[2 * i + 1] = __floats2half2_rn(v.z, v.w);
    }
    uint4* d = (uint4*)(g_dh + base);
    d[0] = reinterpret_cast<uint4*>(h)[0];
    d[1] = reinterpret_cast<uint4*>(h)[1];
}

// ============================================================================
// Kernel 4: block-sparse fp16 GEMM, dense per-nb iteration.
// CTA: 512m x 32n, 8 warps (warp = 64m x 32n). 3-stage cp.async, 2 CTAs/SM.
// grid = (nb=128, mtile=8).
// ============================================================================
__global__ __launch_bounds__(256, 2) void gemm_sparse_kernel(
    const float* __restrict__ bias,   // [N]
    float* __restrict__ out) {        // [M, N]
    extern __shared__ char smem[];
    const uint32_t sb = smem_u32(smem);
    const int tid = threadIdx.x;
    const int wid = tid >> 5;
    const int lane = tid & 31;
    const int nb = blockIdx.x;
    const int mtile = blockIdx.y;

    const int cnt = g_kcount[nb];
    if (tid < KB) ((int*)smem)[tid] = g_klist[nb * KB + tid];
    if (tid < 32)  ((float*)(smem + SMEM_BIAS))[tid] = bias[nb * 32 + tid];
    __syncthreads();
    const int* sk = (const int*)smem;

    const __half* Abase = g_dh + (size_t)(mtile * 512) * KDIM;
    const __half* Wbase = g_wh + (size_t)(nb * 32) * KDIM;

    // ---- stage loader: A 2048 + W 128 16B chunks over 256 threads ----
    auto load_stage = [&](int s, int kb) {
        const uint32_t aT = sb + SMEM_STAGE + s * STAGE_BYTES;
        const uint32_t wT = aT + A_BYTES;
        const __half* ag = Abase + kb * 32;
        const __half* wg = Wbase + kb * 32;
#pragma unroll
        for (int p = 0; p < 8; p++) {
            int c = tid + p * 256;           // 0..2047
            int row = c >> 2, cc = c & 3;
            cp_async16(aT + SWZ(row * 64 + cc * 16),
                       ag + (size_t)row * KDIM + cc * 8);
        }
        if (tid < 128) {
            int row = tid >> 2, cc = tid & 3;
            cp_async16(wT + SWZ(row * 64 + cc * 16),
                       wg + (size_t)row * KDIM + cc * 8);
        }
    };

    float c_[4][4][4] = {};   // [m16-tile][n8-tile][frag]

    // ---- prologue ----
#pragma unroll
    for (int s0 = 0; s0 < STAGES - 1; s0++) {
        if (s0 < cnt) load_stage(s0, sk[s0]);
        CP_ASYNC_COMMIT();
    }

    const int a_r  = (lane & 7) + ((lane >> 3) & 1) * 8;
    const int a_ch = lane >> 4;
    const int b_r  = ((lane >> 4) & 1) * 8 + (lane & 7);
    const int b_ch = (lane >> 3) & 1;

    int s = 0;
    for (int i = 0; i < cnt; i++) {
        CP_ASYNC_WAIT(STAGES - 2);
        __syncthreads();

        int jn = i + STAGES - 1;
        if (jn < cnt) {
            int sj = s + STAGES - 1; if (sj >= STAGES) sj -= STAGES;
            load_stage(sj, sk[jn]);
        }
        CP_ASYNC_COMMIT();

        const uint32_t aT = sb + SMEM_STAGE + s * STAGE_BYTES;
        const uint32_t wT = aT + A_BYTES;
#pragma unroll
        for (int j = 0; j < 2; j++) {        // two k16 steps
            uint32_t bx[4], by[4];
            int ch = 2 * j + b_ch;
            ldsm_x4(wT + SWZ(b_r * 64 + ch * 16), bx);          // nt0, nt1
            ldsm_x4(wT + SWZ((b_r + 16) * 64 + ch * 16), by);   // nt2, nt3
            uint32_t bf[4][2] = {
                {bx[0], bx[1]}, {bx[2], bx[3]},
                {by[0], by[1]}, {by[2], by[3]}
            };
#pragma unroll
            for (int mt = 0; mt < 4; mt++) {
                uint32_t af[4];
                int row = wid * 64 + mt * 16 + a_r;
                ldsm_x4(aT + SWZ(row * 64 + (2 * j + a_ch) * 16), af);
#pragma unroll
                for (int nt = 0; nt < 4; nt++)
                    mma_f16(c_[mt][nt], af, bf[nt]);
            }
        }
        s++; if (s == STAGES) s = 0;
    }

    // ---- epilogue: add bias, store float2 pairs ----
    const float* sbias = (const float*)(smem + SMEM_BIAS);
    const int g = lane >> 2;
    const int qq = lane & 3;
#pragma unroll
    for (int mt = 0; mt < 4; mt++) {
        int row0 = mtile * 512 + wid * 64 + mt * 16 + g;
#pragma unroll
        for (int nt = 0; nt < 4; nt++) {
            int coll = nt * 8 + 2 * qq;
            float b0 = sbias[coll];
            float b1 = sbias[coll + 1];
            float2 v0 = make_float2(c_[mt][nt][0] + b0, c_[mt][nt][1] + b1);
            float2 v1 = make_float2(c_[mt][nt][2] + b0, c_[mt][nt][3] + b1);
            size_t col = (size_t)nb * 32 + coll;
            *(float2*)(out + (size_t)row0 * NDIM + col) = v0;
            *(float2*)(out + (size_t)(row0 + 8) * NDIM + col) = v1;
        }
    }
}

// ============================================================================
// Launch
// ============================================================================
extern "C" void kernel_launch(void* const* d_in, const int* in_sizes, int n_in,
                              void* d_out, int out_size) {
    const float* data   = (const float*)d_in[0];   // [B,S,K] -> [M,K]
    const int*   mask   = (const int*)d_in[1];     // [N,K]
    const float* weight = (const float*)d_in[2];   // [N,K]
    const float* bias   = (const float*)d_in[3];   // [N]
    float* out = (float*)d_out;                    // [M,N]

    mask_w_kernel<<<NB, 512>>>(mask, weight);
    cvt_data_kernel<<<4096, 256>>>(data);
    compact_kernel<<<4, 1024>>>();

    cudaFuncSetAttribute(gemm_sparse_kernel,
                         cudaFuncAttributeMaxDynamicSharedMemorySize, SMEM_TOTAL);
    dim3 grid(NB, MDIM / 512);     // x = nb, y = mtile
    gemm_sparse_kernel<<<grid, 256, SMEM_TOTAL>>>(bias, out);
}

// round 14
// speedup vs baseline: 1.5570x; 1.1452x over previous
#include <cuda_runtime.h>
#include <cuda_fp16.h>
#include <cstdint>

// ============================================================================
// Problem constants
// ============================================================================
#define KDIM 4096
#define NDIM 4096
#define MDIM 4096        // B*S
#define NB   128         // N / 32
#define KB   128         // K / 32

#define STAGES 3
#define A_BYTES (256 * 32 * 2)     // 16384  A tile [256m x 32k] fp16
#define W_BYTES (32 * 32 * 2)      // 2048   W tile [32n x 32k] fp16
#define STAGE_BYTES (A_BYTES + W_BYTES)            // 18432
#define SMEM_BIAS  512                             // 128B (32 floats)
#define SMEM_STAGE 1024
#define SMEM_TOTAL (SMEM_STAGE + STAGES * STAGE_BYTES)  // 56320 -> 4 CTAs/SM

// ============================================================================
// Device globals
// ============================================================================
__device__ int g_bm[NB * KB];                    // block-active bitmap
__device__ int g_klist[NB * KB];                 // per-nb compacted kb list
__device__ int g_kcount[NB];                     // per-nb active count
__device__ __half g_dh[(size_t)MDIM * KDIM];     // data  fp16 (32MB)
__device__ __half g_wh[(size_t)NDIM * KDIM];     // weight fp16 (active blocks only)

// ============================================================================
// Helpers
// ============================================================================
__device__ __forceinline__ uint32_t smem_u32(const void* p) {
    uint32_t a;
    asm("{ .reg .u64 t; cvta.to.shared.u64 t, %1; cvt.u32.u64 %0, t; }"
        : "=r"(a) : "l"(p));
    return a;
}

#define SWZ(off) ((uint32_t)(off) ^ ((((uint32_t)(off)) >> 3) & 0x70))

__device__ __forceinline__ void cp_async16(uint32_t saddr, const void* gaddr) {
    asm volatile("cp.async.cg.shared.global [%0], [%1], 16;"
                 :: "r"(saddr), "l"(gaddr) : "memory");
}
#define CP_ASYNC_COMMIT() asm volatile("cp.async.commit_group;" ::: "memory")
#define CP_ASYNC_WAIT(n)  asm volatile("cp.async.wait_group %0;" :: "n"(n) : "memory")

__device__ __forceinline__ void ldsm_x4(uint32_t addr, uint32_t* r) {
    asm volatile("ldmatrix.sync.aligned.m8n8.x4.shared.b16 {%0,%1,%2,%3}, [%4];"
                 : "=r"(r[0]), "=r"(r[1]), "=r"(r[2]), "=r"(r[3]) : "r"(addr));
}

// m16n8k16 fp16 mma, fp32 accum: D += A * B^T (row.col)
__device__ __forceinline__ void mma_f16(float* c, const uint32_t* a, const uint32_t* b) {
    asm volatile(
        "mma.sync.aligned.m16n8k16.row.col.f32.f16.f16.f32 "
        "{%0,%1,%2,%3}, {%4,%5,%6,%7}, {%8,%9}, {%0,%1,%2,%3};"
        : "+f"(c[0]), "+f"(c[1]), "+f"(c[2]), "+f"(c[3])
        : "r"(a[0]), "r"(a[1]), "r"(a[2]), "r"(a[3]), "r"(b[0]), "r"(b[1]));
}

// ============================================================================
// Kernel 1 (fused prepass): mask pool + active-weight convert + data convert.
// One CTA (512 threads) per nb row-block; each CTA also converts 1/128 of data.
// ============================================================================
__global__ __launch_bounds__(512) void prepass_kernel(
    const int* __restrict__ mask, const float* __restrict__ weight,
    const float* __restrict__ data) {
    __shared__ int sm_bm[KB];
    __shared__ int sm_list[KB];
    __shared__ int sm_cnt;
    const int nb = blockIdx.x;
    const int tid = threadIdx.x;

    if (tid < KB) sm_bm[tid] = 0;
    __syncthreads();

    // --- phase 1: coalesced mask scan; per-thread OR over 32 rows ---
    int acc0 = 0, acc1 = 0;
    const int* mrow = mask + (size_t)(nb * 32) * KDIM;
#pragma unroll 4
    for (int r = 0; r < 32; r++) {
        const int4* p = (const int4*)(mrow + (size_t)r * KDIM);
        int4 v0 = p[tid];
        int4 v1 = p[tid + 512];
        acc0 |= v0.x | v0.y | v0.z | v0.w;
        acc1 |= v1.x | v1.y | v1.z | v1.w;
    }
    if (acc0) sm_bm[tid >> 3] = 1;          // idempotent stores, no atomics
    if (acc1) sm_bm[64 + (tid >> 3)] = 1;
    __syncthreads();

    // --- write bitmap + build local active list ---
    if (tid < KB) g_bm[nb * KB + tid] = sm_bm[tid];
    if (tid == 0) {
        int c = 0;
        for (int kb = 0; kb < KB; kb++)
            if (sm_bm[kb]) sm_list[c++] = kb;
        sm_cnt = c;
    }

    // --- phase 2 (independent): convert this CTA's 1/128 slice of data ---
    // 512 threads x 256 floats = 131072 floats per CTA.
    {
        const size_t cta_base = (size_t)nb * 131072;
#pragma unroll
        for (int qk = 0; qk < 16; qk++) {
            size_t base = cta_base + ((size_t)qk * 512 + tid) * 16;
            const float4* s = (const float4*)(data + base);
            __half2 h[8];
#pragma unroll
            for (int i = 0; i < 4; i++) {
                float4 v = s[i];
                h[2 * i]     = __floats2half2_rn(v.x, v.y);
                h[2 * i + 1] = __floats2half2_rn(v.z, v.w);
            }
            uint4* d = (uint4*)(g_dh + base);
            d[0] = reinterpret_cast<uint4*>(h)[0];
            d[1] = reinterpret_cast<uint4*>(h)[1];
        }
    }
    __syncthreads();

    // --- phase 3: convert active weight blocks (32x32) to fp16 ---
    const int cnt = sm_cnt;
    const int row = tid >> 4;          // 0..31
    const int pos = (tid & 15) * 2;    // 0..30
    for (int j = 0; j < cnt; j++) {
        int kb = sm_list[j];
        size_t off = (size_t)(nb * 32 + row) * KDIM + (size_t)kb * 32 + pos;
        float2 v = *(const float2*)(weight + off);
        *(__half2*)(g_wh + off) = __floats2half2_rn(v.x, v.y);
    }
}

// ============================================================================
// Kernel 2: compact per-nb active kb list (deterministic order).
// ============================================================================
__global__ __launch_bounds__(1024) void compact_kernel() {
    int nb = blockIdx.x * 32 + (threadIdx.x >> 5);
    int lane = threadIdx.x & 31;
    int count = 0;
#pragma unroll
    for (int r = 0; r < 4; r++) {
        int kb = r * 32 + lane;
        int a = g_bm[nb * KB + kb];
        unsigned bal = __ballot_sync(0xffffffffu, a);
        int pos = count + __popc(bal & ((1u << lane) - 1u));
        if (a) g_klist[nb * KB + pos] = kb;
        count += __popc(bal);
    }
    if (lane == 0) g_kcount[nb] = count;
}

// ============================================================================
// Kernel 3: block-sparse fp16 GEMM, dense per-nb iteration.
// CTA: 256m x 32n, 4 warps (warp = 64m x 32n). 3-stage cp.async, 4 CTAs/SM.
// grid = (nb=128, mtile=16).
// ============================================================================
__global__ __launch_bounds__(128, 4) void gemm_sparse_kernel(
    const float* __restrict__ bias,   // [N]
    float* __restrict__ out) {        // [M, N]
    extern __shared__ char smem[];
    const uint32_t sb = smem_u32(smem);
    const int tid = threadIdx.x;
    const int wid = tid >> 5;
    const int lane = tid & 31;
    const int nb = blockIdx.x;
    const int mtile = blockIdx.y;

    const int cnt = g_kcount[nb];
    if (tid < KB) ((int*)smem)[tid] = g_klist[nb * KB + tid];
    if (tid < 32) ((float*)(smem + SMEM_BIAS))[tid] = bias[nb * 32 + tid];
    __syncthreads();
    const int* sk = (const int*)smem;

    const __half* Abase = g_dh + (size_t)(mtile * 256) * KDIM;
    const __half* Wbase = g_wh + (size_t)(nb * 32) * KDIM;

    // ---- stage loader: A 1024 + W 128 16B chunks over 128 threads ----
    auto load_stage = [&](int s, int kb) {
        const uint32_t aT = sb + SMEM_STAGE + s * STAGE_BYTES;
        const uint32_t wT = aT + A_BYTES;
        const __half* ag = Abase + kb * 32;
        const __half* wg = Wbase + kb * 32;
#pragma unroll
        for (int p = 0; p < 8; p++) {
            int c = tid + p * 128;           // 0..1023
            int row = c >> 2, cc = c & 3;
            cp_async16(aT + SWZ(row * 64 + cc * 16),
                       ag + (size_t)row * KDIM + cc * 8);
        }
        {
            int row = tid >> 2, cc = tid & 3;
            cp_async16(wT + SWZ(row * 64 + cc * 16),
                       wg + (size_t)row * KDIM + cc * 8);
        }
    };

    float c_[4][4][4] = {};   // [m16-tile][n8-tile][frag]

    // ---- prologue ----
#pragma unroll
    for (int s0 = 0; s0 < STAGES - 1; s0++) {
        if (s0 < cnt) load_stage(s0, sk[s0]);
        CP_ASYNC_COMMIT();
    }

    const int a_r  = (lane & 7) + ((lane >> 3) & 1) * 8;
    const int a_ch = lane >> 4;
    const int b_r  = ((lane >> 4) & 1) * 8 + (lane & 7);
    const int b_ch = (lane >> 3) & 1;

    int s = 0;
    for (int i = 0; i < cnt; i++) {
        CP_ASYNC_WAIT(STAGES - 2);
        __syncthreads();

        int jn = i + STAGES - 1;
        if (jn < cnt) {
            int sj = s + STAGES - 1; if (sj >= STAGES) sj -= STAGES;
            load_stage(sj, sk[jn]);
        }
        CP_ASYNC_COMMIT();

        const uint32_t aT = sb + SMEM_STAGE + s * STAGE_BYTES;
        const uint32_t wT = aT + A_BYTES;
#pragma unroll
        for (int j = 0; j < 2; j++) {        // two k16 steps
            uint32_t bx[4], by[4];
            int ch = 2 * j + b_ch;
            ldsm_x4(wT + SWZ(b_r * 64 + ch * 16), bx);          // nt0, nt1
            ldsm_x4(wT + SWZ((b_r + 16) * 64 + ch * 16), by);   // nt2, nt3
            uint32_t bf[4][2] = {
                {bx[0], bx[1]}, {bx[2], bx[3]},
                {by[0], by[1]}, {by[2], by[3]}
            };
#pragma unroll
            for (int mt = 0; mt < 4; mt++) {
                uint32_t af[4];
                int row = wid * 64 + mt * 16 + a_r;
                ldsm_x4(aT + SWZ(row * 64 + (2 * j + a_ch) * 16), af);
#pragma unroll
                for (int nt = 0; nt < 4; nt++)
                    mma_f16(c_[mt][nt], af, bf[nt]);
            }
        }
        s++; if (s == STAGES) s = 0;
    }

    // ---- epilogue: add bias, store float2 pairs ----
    const float* sbias = (const float*)(smem + SMEM_BIAS);
    const int g = lane >> 2;
    const int qq = lane & 3;
#pragma unroll
    for (int mt = 0; mt < 4; mt++) {
        int row0 = mtile * 256 + wid * 64 + mt * 16 + g;
#pragma unroll
        for (int nt = 0; nt < 4; nt++) {
            int coll = nt * 8 + 2 * qq;
            float b0 = sbias[coll];
            float b1 = sbias[coll + 1];
            float2 v0 = make_float2(c_[mt][nt][0] + b0, c_[mt][nt][1] + b1);
            float2 v1 = make_float2(c_[mt][nt][2] + b0, c_[mt][nt][3] + b1);
            size_t col = (size_t)nb * 32 + coll;
            *(float2*)(out + (size_t)row0 * NDIM + col) = v0;
            *(float2*)(out + (size_t)(row0 + 8) * NDIM + col) = v1;
        }
    }
}

// ============================================================================
// Launch
// ============================================================================
extern "C" void kernel_launch(void* const* d_in, const int* in_sizes, int n_in,
                              void* d_out, int out_size) {
    const float* data   = (const float*)d_in[0];   // [B,S,K] -> [M,K]
    const int*   mask   = (const int*)d_in[1];     // [N,K]
    const float* weight = (const float*)d_in[2];   // [N,K]
    const float* bias   = (const float*)d_in[3];   // [N]
    float* out = (float*)d_out;                    // [M,N]

    prepass_kernel<<<NB, 512>>>(mask, weight, data);
    compact_kernel<<<4, 1024>>>();

    cudaFuncSetAttribute(gemm_sparse_kernel,
                         cudaFuncAttributeMaxDynamicSharedMemorySize, SMEM_TOTAL);
    dim3 grid(NB, MDIM / 256);     // x = nb, y = mtile
    gemm_sparse_kernel<<<grid, 128, SMEM_TOTAL>>>(bias, out);
}